// round 5
// baseline (speedup 1.0000x reference)
#include <cuda_runtime.h>
#include <math.h>

#define SEQ    2048
#define DMODEL 1024
#define NHEAD  16
#define DHEAD  64
#define BATCH  2
#define NTOK   (BATCH*SEQ)

// ---------------- scratch (device globals; no allocation allowed) ------------
__device__ float g_pe[SEQ*DMODEL];
__device__ float g_xn[NTOK*DMODEL];
__device__ float g_q [NTOK*DMODEL];
__device__ float g_k [NTOK*DMODEL];
__device__ float g_v [NTOK*DMODEL];
__device__ float g_p [SEQ*DMODEL];
__device__ float g_head[NTOK*DMODEL];
__device__ float g_pos[(size_t)BATCH*NHEAD*SEQ*SEQ];   // 512 MB

// ---------------- sinusoidal positional encoding ----------------------------
__global__ void pe_kernel(float* __restrict__ pe) {
    int idx = blockIdx.x * blockDim.x + threadIdx.x;
    if (idx >= SEQ * (DMODEL/2)) return;
    int t   = idx % (DMODEL/2);
    int pos = idx / (DMODEL/2);
    float div = expf(-logf(10000.0f) * (2.0f * (float)t) / (float)DMODEL);
    float ang = (float)pos * div;
    pe[pos*DMODEL + 2*t    ] = sinf(ang);
    pe[pos*DMODEL + 2*t + 1] = cosf(ang);
}

// ---------------- layernorm --------------------------------------------------
__global__ void ln_kernel(const float* __restrict__ x,
                          const float* __restrict__ g,
                          const float* __restrict__ b,
                          float* __restrict__ out) {
    int row = blockIdx.x;
    int tid = threadIdx.x;                  // 256 threads, 4 elems each
    const float4* xr = (const float4*)(x + (size_t)row * DMODEL);
    float4 xv = xr[tid];
    float s  = xv.x + xv.y + xv.z + xv.w;
    float sq = xv.x*xv.x + xv.y*xv.y + xv.z*xv.z + xv.w*xv.w;
    #pragma unroll
    for (int off = 16; off > 0; off >>= 1) {
        s  += __shfl_xor_sync(0xffffffffu, s,  off);
        sq += __shfl_xor_sync(0xffffffffu, sq, off);
    }
    __shared__ float ss[8], sqs[8];
    __shared__ float mean_s, rstd_s;
    int wid = tid >> 5, lane = tid & 31;
    if (lane == 0) { ss[wid] = s; sqs[wid] = sq; }
    __syncthreads();
    if (tid == 0) {
        float S = 0.f, Q = 0.f;
        #pragma unroll
        for (int i = 0; i < 8; i++) { S += ss[i]; Q += sqs[i]; }
        float mean = S / (float)DMODEL;
        float var  = Q / (float)DMODEL - mean * mean;
        mean_s = mean;
        rstd_s = rsqrtf(var + 1e-5f);
    }
    __syncthreads();
    float mean = mean_s, rstd = rstd_s;
    float4 gv = ((const float4*)g)[tid];
    float4 bv = ((const float4*)b)[tid];
    float4 o;
    o.x = (xv.x - mean) * rstd * gv.x + bv.x;
    o.y = (xv.y - mean) * rstd * gv.y + bv.y;
    o.z = (xv.z - mean) * rstd * gv.z + bv.z;
    o.w = (xv.w - mean) * rstd * gv.w + bv.w;
    ((float4*)(out + (size_t)row * DMODEL))[tid] = o;
}

// ---------------- generic SGEMM: C = A[MxK] * B[KxN] (+bias) -----------------
// 128x128 tile, BK=8, 256 threads, 8x8 per thread.
__global__ void __launch_bounds__(256) sgemm_bias(
    const float* __restrict__ A, const float* __restrict__ B,
    const float* __restrict__ bias, float* __restrict__ C,
    int M, int N, int K) {
    __shared__ float As[8][128];
    __shared__ float Bs[8][128];
    int tid = threadIdx.x;
    int bx = blockIdx.x, by = blockIdx.y;
    int arow = tid >> 1, acol = (tid & 1) * 4;
    int brow = tid >> 5, bcol = (tid & 31) * 4;
    int tx = tid & 15, ty = tid >> 4;
    const float* Ap = A + (size_t)(by*128 + arow) * K + acol;
    const float* Bp = B + (size_t)brow * N + bx*128 + bcol;
    float acc[8][8];
    #pragma unroll
    for (int i = 0; i < 8; i++)
        #pragma unroll
        for (int j = 0; j < 8; j++) acc[i][j] = 0.f;

    for (int k0 = 0; k0 < K; k0 += 8) {
        float4 a4 = *(const float4*)(Ap + k0);
        float4 b4 = *(const float4*)(Bp + (size_t)k0 * N);
        As[acol+0][arow] = a4.x; As[acol+1][arow] = a4.y;
        As[acol+2][arow] = a4.z; As[acol+3][arow] = a4.w;
        *(float4*)&Bs[brow][bcol] = b4;
        __syncthreads();
        #pragma unroll
        for (int k = 0; k < 8; k++) {
            float ar[8], br[8];
            *(float4*)&ar[0] = *(const float4*)&As[k][ty*8];
            *(float4*)&ar[4] = *(const float4*)&As[k][ty*8+4];
            *(float4*)&br[0] = *(const float4*)&Bs[k][tx*8];
            *(float4*)&br[4] = *(const float4*)&Bs[k][tx*8+4];
            #pragma unroll
            for (int i = 0; i < 8; i++)
                #pragma unroll
                for (int j = 0; j < 8; j++)
                    acc[i][j] += ar[i] * br[j];
        }
        __syncthreads();
    }
    int col = bx*128 + tx*8;
    float bb[8];
    #pragma unroll
    for (int j = 0; j < 8; j++) bb[j] = bias ? bias[col+j] : 0.f;
    #pragma unroll
    for (int i = 0; i < 8; i++) {
        int row = by*128 + ty*8 + i;
        float* Cp = C + (size_t)row * N + col;
        float4 o0, o1;
        o0.x = acc[i][0]+bb[0]; o0.y = acc[i][1]+bb[1];
        o0.z = acc[i][2]+bb[2]; o0.w = acc[i][3]+bb[3];
        o1.x = acc[i][4]+bb[4]; o1.y = acc[i][5]+bb[5];
        o1.z = acc[i][6]+bb[6]; o1.w = acc[i][7]+bb[7];
        *(float4*)Cp = o0; *(float4*)(Cp+4) = o1;
    }
}

// ---------------- pos = (q + v_bias) @ p^T per (b,h) -------------------------
// grid (S/64 [j], S/64 [i], B*H), 64x64 tile, K=64, 4x4 per thread.
__global__ void __launch_bounds__(256) posgemm_kernel(
    const float* __restrict__ q, const float* __restrict__ p,
    const float* __restrict__ vbias, float* __restrict__ pos) {
    int jt = blockIdx.x, it = blockIdx.y, bh = blockIdx.z;
    int b = bh >> 4, h = bh & 15;
    __shared__ float Qt[64][64];   // [d][i]
    __shared__ float Pt[64][64];   // [d][j]
    int tid = threadIdx.x;
    int tx = tid & 15, ty = tid >> 4;
    int lr = tid >> 4;
    int lc = (tid & 15) * 4;
    float4 vb = *(const float4*)&vbias[h*DHEAD + lc];
    #pragma unroll
    for (int l = 0; l < 4; l++) {
        int row = lr + l*16;
        float4 a = *(const float4*)&q[((size_t)(b*SEQ + it*64 + row)*NHEAD + h)*DHEAD + lc];
        Qt[lc+0][row] = a.x + vb.x; Qt[lc+1][row] = a.y + vb.y;
        Qt[lc+2][row] = a.z + vb.z; Qt[lc+3][row] = a.w + vb.w;
        float4 pp = *(const float4*)&p[((size_t)(jt*64 + row)*NHEAD + h)*DHEAD + lc];
        Pt[lc+0][row] = pp.x; Pt[lc+1][row] = pp.y;
        Pt[lc+2][row] = pp.z; Pt[lc+3][row] = pp.w;
    }
    __syncthreads();
    float acc[4][4];
    #pragma unroll
    for (int u = 0; u < 4; u++)
        #pragma unroll
        for (int v = 0; v < 4; v++) acc[u][v] = 0.f;
    #pragma unroll
    for (int d = 0; d < 64; d++) {
        float a_[4], b_[4];
        *(float4*)a_ = *(const float4*)&Qt[d][ty*4];
        *(float4*)b_ = *(const float4*)&Pt[d][tx*4];
        #pragma unroll
        for (int u = 0; u < 4; u++)
            #pragma unroll
            for (int v = 0; v < 4; v++)
                acc[u][v] += a_[u] * b_[v];
    }
    #pragma unroll
    for (int u = 0; u < 4; u++) {
        float* dst = pos + ((size_t)bh*SEQ + it*64 + ty*4 + u)*SEQ + jt*64 + tx*4;
        float4 o; o.x = acc[u][0]; o.y = acc[u][1]; o.z = acc[u][2]; o.w = acc[u][3];
        *(float4*)dst = o;
    }
}

// ---------------- fused flash attention with relative shift ------------------
// grid (S/64 [i-tile], B*H). Online softmax over j-tiles of 64.
// shifted_pos(i,j): j<=i -> pos[i, S-1-i+j]; j==i+1 -> 0; j>=i+2 -> pos[i+1, j-i-2]
__global__ void __launch_bounds__(256) attn_kernel(
    const float* __restrict__ q, const float* __restrict__ k,
    const float* __restrict__ v, const float* __restrict__ pos,
    const float* __restrict__ ubias, float* __restrict__ head) {
    int it = blockIdx.x, bh = blockIdx.y;
    int b = bh >> 4, h = bh & 15;
    int i0 = it * 64;
    __shared__ float Qt[64][64];   // (q+u) transposed [d][i]
    __shared__ float KV[64][64];   // K transposed [d][j], then V direct [j][c]
    __shared__ float Pt[64][64];   // probabilities transposed [j][i]
    int tid = threadIdx.x;
    int tx = tid & 15, ty = tid >> 4;
    int lr = tid >> 4;
    int lc = (tid & 15) * 4;
    const float scale = 0.125f;   // dh^-0.5, dh=64

    float4 ub = *(const float4*)&ubias[h*DHEAD + lc];
    #pragma unroll
    for (int l = 0; l < 4; l++) {
        int row = lr + l*16;
        float4 a = *(const float4*)&q[((size_t)(b*SEQ + i0 + row)*NHEAD + h)*DHEAD + lc];
        Qt[lc+0][row] = a.x + ub.x; Qt[lc+1][row] = a.y + ub.y;
        Qt[lc+2][row] = a.z + ub.z; Qt[lc+3][row] = a.w + ub.w;
    }

    float mrow[4], lsum[4], acc[4][4];
    #pragma unroll
    for (int u = 0; u < 4; u++) {
        mrow[u] = -1e30f; lsum[u] = 0.f;
        #pragma unroll
        for (int vv = 0; vv < 4; vv++) acc[u][vv] = 0.f;
    }

    for (int j0 = 0; j0 < SEQ; j0 += 64) {
        __syncthreads();   // Qt ready (iter 0) / prev PV done reading KV,Pt
        #pragma unroll
        for (int l = 0; l < 4; l++) {
            int row = lr + l*16;
            float4 a = *(const float4*)&k[((size_t)(b*SEQ + j0 + row)*NHEAD + h)*DHEAD + lc];
            KV[lc+0][row] = a.x; KV[lc+1][row] = a.y;
            KV[lc+2][row] = a.z; KV[lc+3][row] = a.w;
        }
        __syncthreads();

        float sc[4][4];
        #pragma unroll
        for (int u = 0; u < 4; u++)
            #pragma unroll
            for (int vv = 0; vv < 4; vv++) sc[u][vv] = 0.f;
        #pragma unroll
        for (int d = 0; d < 64; d++) {
            float a_[4], b_[4];
            *(float4*)a_ = *(const float4*)&Qt[d][ty*4];
            *(float4*)b_ = *(const float4*)&KV[d][tx*4];
            #pragma unroll
            for (int u = 0; u < 4; u++)
                #pragma unroll
                for (int vv = 0; vv < 4; vv++)
                    sc[u][vv] += a_[u] * b_[vv];
        }

        #pragma unroll
        for (int u = 0; u < 4; u++) {
            int gi = i0 + ty*4 + u;
            const float* row_le = pos + ((size_t)bh*SEQ + gi)*SEQ;
            float tmax = -1e30f;
            #pragma unroll
            for (int vv = 0; vv < 4; vv++) {
                int gj = j0 + tx*4 + vv;
                float pvv;
                if (gj <= gi)          pvv = row_le[SEQ - 1 - gi + gj];
                else if (gj == gi + 1) pvv = 0.f;
                else                   pvv = row_le[(size_t)SEQ + (gj - gi - 2)]; // row gi+1
                float s = (sc[u][vv] + pvv) * scale;
                sc[u][vv] = s;
                tmax = fmaxf(tmax, s);
            }
            #pragma unroll
            for (int off = 8; off > 0; off >>= 1)
                tmax = fmaxf(tmax, __shfl_xor_sync(0xffffffffu, tmax, off));
            float mnew = fmaxf(mrow[u], tmax);
            float corr = __expf(mrow[u] - mnew);
            float rs = 0.f;
            #pragma unroll
            for (int vv = 0; vv < 4; vv++) {
                float pw = __expf(sc[u][vv] - mnew);
                sc[u][vv] = pw;
                rs += pw;
            }
            #pragma unroll
            for (int off = 8; off > 0; off >>= 1)
                rs += __shfl_xor_sync(0xffffffffu, rs, off);
            lsum[u] = lsum[u] * corr + rs;
            mrow[u] = mnew;
            #pragma unroll
            for (int vv = 0; vv < 4; vv++) {
                acc[u][vv] *= corr;
                Pt[tx*4+vv][ty*4+u] = sc[u][vv];
            }
        }
        __syncthreads();   // scores done reading KV; Pt written

        #pragma unroll
        for (int l = 0; l < 4; l++) {
            int row = lr + l*16;
            *(float4*)&KV[row][lc] =
                *(const float4*)&v[((size_t)(b*SEQ + j0 + row)*NHEAD + h)*DHEAD + lc];
        }
        __syncthreads();

        #pragma unroll
        for (int jj = 0; jj < 64; jj++) {
            float a_[4], b_[4];
            *(float4*)a_ = *(const float4*)&Pt[jj][ty*4];
            *(float4*)b_ = *(const float4*)&KV[jj][tx*4];
            #pragma unroll
            for (int u = 0; u < 4; u++)
                #pragma unroll
                for (int vv = 0; vv < 4; vv++)
                    acc[u][vv] += a_[u] * b_[vv];
        }
    }

    #pragma unroll
    for (int u = 0; u < 4; u++) {
        float inv = 1.f / lsum[u];
        float4 o;
        o.x = acc[u][0]*inv; o.y = acc[u][1]*inv;
        o.z = acc[u][2]*inv; o.w = acc[u][3]*inv;
        *(float4*)&head[((size_t)(b*SEQ + i0 + ty*4 + u))*DMODEL + h*DHEAD + tx*4] = o;
    }
}

// ---------------- launch -----------------------------------------------------
extern "C" void kernel_launch(void* const* d_in, const int* in_sizes, int n_in,
                              void* d_out, int out_size) {
    const float* x    = (const float*)d_in[0];
    const float* ln_g = (const float*)d_in[1];
    const float* ln_b = (const float*)d_in[2];
    const float* Wq   = (const float*)d_in[3];
    const float* bq   = (const float*)d_in[4];
    const float* Wk   = (const float*)d_in[5];
    const float* bk   = (const float*)d_in[6];
    const float* Wv   = (const float*)d_in[7];
    const float* bv   = (const float*)d_in[8];
    const float* Wp   = (const float*)d_in[9];
    const float* Wo   = (const float*)d_in[10];
    const float* bo   = (const float*)d_in[11];
    const float* u_b  = (const float*)d_in[12];
    const float* v_b  = (const float*)d_in[13];
    float* out = (float*)d_out;

    float *pe, *xn, *qb, *kb, *vb, *pb, *hb, *posb;
    cudaGetSymbolAddress((void**)&pe,   g_pe);
    cudaGetSymbolAddress((void**)&xn,   g_xn);
    cudaGetSymbolAddress((void**)&qb,   g_q);
    cudaGetSymbolAddress((void**)&kb,   g_k);
    cudaGetSymbolAddress((void**)&vb,   g_v);
    cudaGetSymbolAddress((void**)&pb,   g_p);
    cudaGetSymbolAddress((void**)&hb,   g_head);
    cudaGetSymbolAddress((void**)&posb, g_pos);

    // 1. sinusoidal PE
    pe_kernel<<<(SEQ*(DMODEL/2) + 255)/256, 256>>>(pe);
    // 2. layernorm
    ln_kernel<<<NTOK, 256>>>(x, ln_g, ln_b, xn);
    // 3. projections
    dim3 gproj(DMODEL/128, NTOK/128);
    sgemm_bias<<<gproj, 256>>>(xn, Wq, bq, qb, NTOK, DMODEL, DMODEL);
    sgemm_bias<<<gproj, 256>>>(xn, Wk, bk, kb, NTOK, DMODEL, DMODEL);
    sgemm_bias<<<gproj, 256>>>(xn, Wv, bv, vb, NTOK, DMODEL, DMODEL);
    dim3 gp(DMODEL/128, SEQ/128);
    sgemm_bias<<<gp, 256>>>(pe, Wp, nullptr, pb, SEQ, DMODEL, DMODEL);
    // 4. pos scores (pre-shift) per head
    dim3 gpos(SEQ/64, SEQ/64, BATCH*NHEAD);
    posgemm_kernel<<<gpos, 256>>>(qb, pb, v_b, posb);
    // 5. fused attention (content + shifted pos + softmax + PV)
    dim3 gattn(SEQ/64, BATCH*NHEAD);
    attn_kernel<<<gattn, 256>>>(qb, kb, vb, posb, u_b, hb);
    // 6. output projection
    sgemm_bias<<<gproj, 256>>>(hb, Wo, bo, out, NTOK, DMODEL, DMODEL);
}

// round 7
// speedup vs baseline: 1.1481x; 1.1481x over previous
#include <cuda_runtime.h>
#include <math.h>
#include <stdint.h>

#define SEQ    2048
#define DMODEL 1024
#define NHEAD  16
#define DHEAD  64
#define BATCH  2
#define NTOK   (BATCH*SEQ)

// ---------------- scratch (device globals; no allocation allowed) ------------
__device__ float g_pe[SEQ*DMODEL];
__device__ float g_xn[NTOK*DMODEL];
__device__ float g_q [NTOK*DMODEL];
__device__ float g_k [NTOK*DMODEL];
__device__ float g_v [NTOK*DMODEL];
__device__ float g_p [SEQ*DMODEL];
__device__ float g_head[NTOK*DMODEL];
__device__ float g_pos[(size_t)BATCH*NHEAD*SEQ*SEQ];   // 512 MB

// ---------------- helpers ----------------------------------------------------
__device__ __forceinline__ uint32_t f2tf(float f) {
    uint32_t r; asm("cvt.rna.tf32.f32 %0, %1;\n" : "=r"(r) : "f"(f)); return r;
}
// 3xTF32 split: x = hi + lo (hi = tf32 round of x, lo = tf32 round of residual)
__device__ __forceinline__ void tf32_split(float x, uint32_t& h, uint32_t& l) {
    h = f2tf(x);
    l = f2tf(x - __uint_as_float(h));
}

#define MMA_TF32(d, a, b) \
    asm volatile("mma.sync.aligned.m16n8k8.row.col.f32.tf32.tf32.f32 " \
        "{%0,%1,%2,%3}, {%4,%5,%6,%7}, {%8,%9}, {%0,%1,%2,%3};\n" \
        : "+f"((d)[0]), "+f"((d)[1]), "+f"((d)[2]), "+f"((d)[3]) \
        : "r"((a)[0]), "r"((a)[1]), "r"((a)[2]), "r"((a)[3]), \
          "r"((b)[0]), "r"((b)[1]))

__device__ __forceinline__ void cp16(uint32_t smem, const void* gmem) {
    asm volatile("cp.async.cg.shared.global [%0], [%1], 16;\n"
                 :: "r"(smem), "l"(gmem));
}
#define CP_COMMIT() asm volatile("cp.async.commit_group;\n" ::: "memory")
#define CP_WAIT(N)  asm volatile("cp.async.wait_group %0;\n" :: "n"(N) : "memory")

// ---------------- sinusoidal positional encoding ----------------------------
__global__ void pe_kernel(float* __restrict__ pe) {
    int idx = blockIdx.x * blockDim.x + threadIdx.x;
    if (idx >= SEQ * (DMODEL/2)) return;
    int t   = idx % (DMODEL/2);
    int pos = idx / (DMODEL/2);
    float div = expf(-logf(10000.0f) * (2.0f * (float)t) / (float)DMODEL);
    float ang = (float)pos * div;
    pe[pos*DMODEL + 2*t    ] = sinf(ang);
    pe[pos*DMODEL + 2*t + 1] = cosf(ang);
}

// ---------------- layernorm --------------------------------------------------
__global__ void ln_kernel(const float* __restrict__ x,
                          const float* __restrict__ g,
                          const float* __restrict__ b,
                          float* __restrict__ out) {
    int row = blockIdx.x;
    int tid = threadIdx.x;
    const float4* xr = (const float4*)(x + (size_t)row * DMODEL);
    float4 xv = xr[tid];
    float s  = xv.x + xv.y + xv.z + xv.w;
    float sq = xv.x*xv.x + xv.y*xv.y + xv.z*xv.z + xv.w*xv.w;
    #pragma unroll
    for (int off = 16; off > 0; off >>= 1) {
        s  += __shfl_xor_sync(0xffffffffu, s,  off);
        sq += __shfl_xor_sync(0xffffffffu, sq, off);
    }
    __shared__ float ss[8], sqs[8];
    __shared__ float mean_s, rstd_s;
    int wid = tid >> 5, lane = tid & 31;
    if (lane == 0) { ss[wid] = s; sqs[wid] = sq; }
    __syncthreads();
    if (tid == 0) {
        float S = 0.f, Q = 0.f;
        #pragma unroll
        for (int i = 0; i < 8; i++) { S += ss[i]; Q += sqs[i]; }
        float mean = S / (float)DMODEL;
        float var  = Q / (float)DMODEL - mean * mean;
        mean_s = mean;
        rstd_s = rsqrtf(var + 1e-5f);
    }
    __syncthreads();
    float mean = mean_s, rstd = rstd_s;
    float4 gv = ((const float4*)g)[tid];
    float4 bv = ((const float4*)b)[tid];
    float4 o;
    o.x = (xv.x - mean) * rstd * gv.x + bv.x;
    o.y = (xv.y - mean) * rstd * gv.y + bv.y;
    o.z = (xv.z - mean) * rstd * gv.z + bv.z;
    o.w = (xv.w - mean) * rstd * gv.w + bv.w;
    ((float4*)(out + (size_t)row * DMODEL))[tid] = o;
}

// ---------------- 3xTF32 tensor-core SGEMM: C = A[MxK]*B[KxN] (+bias) --------
// 128x128 tile, BK=16, 256 threads = 8 warps (4m x 2n), warp tile 32x64.
__global__ void __launch_bounds__(256) sgemm_tf32(
    const float* __restrict__ A, const float* __restrict__ B,
    const float* __restrict__ bias, float* __restrict__ C,
    int M, int N, int K) {
    __shared__ float As[2][128][20];
    __shared__ float Bs[2][16][136];
    int tid = threadIdx.x;
    int bx = blockIdx.x, by = blockIdx.y;
    int w = tid >> 5, lane = tid & 31;
    int gid = lane >> 2, tg = lane & 3;
    int wm = w >> 1, wn = w & 1;

    int ia  = tid * 2;
    int ar0 = ia >> 2,       ac0 = (ia & 3) * 4;
    int ar1 = (ia+1) >> 2,   ac1 = ((ia+1) & 3) * 4;
    int br0 = ia >> 5,       bc0 = (ia & 31) * 4;
    int br1 = (ia+1) >> 5,   bc1 = ((ia+1) & 31) * 4;

    uint32_t sA = (uint32_t)__cvta_generic_to_shared(&As[0][0][0]);
    uint32_t sB = (uint32_t)__cvta_generic_to_shared(&Bs[0][0][0]);
    const float* Ab = A + (size_t)by * 128 * K;
    const float* Bb = B + bx * 128;

    float acc[2][8][4];
    #pragma unroll
    for (int mt = 0; mt < 2; mt++)
        #pragma unroll
        for (int nt = 0; nt < 8; nt++)
            #pragma unroll
            for (int r = 0; r < 4; r++) acc[mt][nt][r] = 0.f;

    int NT = K >> 4;
    {
        int k0 = 0, buf = 0;
        cp16(sA + (uint32_t)(((buf*128 + ar0)*20 + ac0)*4), Ab + (size_t)ar0*K + k0 + ac0);
        cp16(sA + (uint32_t)(((buf*128 + ar1)*20 + ac1)*4), Ab + (size_t)ar1*K + k0 + ac1);
        cp16(sB + (uint32_t)(((buf*16  + br0)*136 + bc0)*4), Bb + (size_t)(k0+br0)*N + bc0);
        cp16(sB + (uint32_t)(((buf*16  + br1)*136 + bc1)*4), Bb + (size_t)(k0+br1)*N + bc1);
        CP_COMMIT();
    }

    for (int t = 0; t < NT; t++) {
        if (t + 1 < NT) {
            int k0 = (t+1) * 16, buf = (t+1) & 1;
            cp16(sA + (uint32_t)(((buf*128 + ar0)*20 + ac0)*4), Ab + (size_t)ar0*K + k0 + ac0);
            cp16(sA + (uint32_t)(((buf*128 + ar1)*20 + ac1)*4), Ab + (size_t)ar1*K + k0 + ac1);
            cp16(sB + (uint32_t)(((buf*16  + br0)*136 + bc0)*4), Bb + (size_t)(k0+br0)*N + bc0);
            cp16(sB + (uint32_t)(((buf*16  + br1)*136 + bc1)*4), Bb + (size_t)(k0+br1)*N + bc1);
            CP_COMMIT();
            CP_WAIT(1);
        } else {
            CP_WAIT(0);
        }
        __syncthreads();
        int buf = t & 1;
        #pragma unroll
        for (int ks = 0; ks < 16; ks += 8) {
            uint32_t ah[2][4], al[2][4];
            #pragma unroll
            for (int mt = 0; mt < 2; mt++) {
                int mB = wm*32 + mt*16;
                tf32_split(As[buf][mB+gid  ][ks+tg  ], ah[mt][0], al[mt][0]);
                tf32_split(As[buf][mB+gid+8][ks+tg  ], ah[mt][1], al[mt][1]);
                tf32_split(As[buf][mB+gid  ][ks+tg+4], ah[mt][2], al[mt][2]);
                tf32_split(As[buf][mB+gid+8][ks+tg+4], ah[mt][3], al[mt][3]);
            }
            #pragma unroll
            for (int nt = 0; nt < 8; nt++) {
                uint32_t bh[2], bl[2];
                int nB = wn*64 + nt*8;
                tf32_split(Bs[buf][ks+tg  ][nB+gid], bh[0], bl[0]);
                tf32_split(Bs[buf][ks+tg+4][nB+gid], bh[1], bl[1]);
                MMA_TF32(acc[0][nt], ah[0], bh);
                MMA_TF32(acc[1][nt], ah[1], bh);
                MMA_TF32(acc[0][nt], ah[0], bl);
                MMA_TF32(acc[1][nt], ah[1], bl);
                MMA_TF32(acc[0][nt], al[0], bh);
                MMA_TF32(acc[1][nt], al[1], bh);
            }
        }
        __syncthreads();
    }

    #pragma unroll
    for (int mt = 0; mt < 2; mt++) {
        int row0 = by*128 + wm*32 + mt*16 + gid;
        #pragma unroll
        for (int nt = 0; nt < 8; nt++) {
            int col = bx*128 + wn*64 + nt*8 + 2*tg;
            float bv0 = 0.f, bv1 = 0.f;
            if (bias) { bv0 = bias[col]; bv1 = bias[col+1]; }
            *(float2*)&C[(size_t)row0*N + col] =
                make_float2(acc[mt][nt][0] + bv0, acc[mt][nt][1] + bv1);
            *(float2*)&C[(size_t)(row0+8)*N + col] =
                make_float2(acc[mt][nt][2] + bv0, acc[mt][nt][3] + bv1);
        }
    }
}

// ---------------- pos = (q + v_bias) @ p^T per (b,h), 3xTF32 MMA -------------
__global__ void __launch_bounds__(256) posgemm_tf32(
    const float* __restrict__ q, const float* __restrict__ p,
    const float* __restrict__ vbias, float* __restrict__ pos) {
    __shared__ float Qs[64][72];
    __shared__ float Rs[64][72];
    int jt = blockIdx.x, itile = blockIdx.y, bh = blockIdx.z;
    int b = bh >> 4, h = bh & 15;
    int i0 = itile*64, j0 = jt*64;
    int tid = threadIdx.x, w = tid >> 5, lane = tid & 31;
    int gid = lane >> 2, tg = lane & 3;
    int wm = w >> 1, wn = w & 1;

    #pragma unroll
    for (int t = 0; t < 4; t++) {
        int idx = tid + t*256;
        int row = idx >> 4, dc = (idx & 15) * 4;
        float4 a = *(const float4*)(q + (size_t)(b*SEQ + i0 + row)*DMODEL + h*DHEAD + dc);
        float4 vb = *(const float4*)(vbias + h*DHEAD + dc);
        a.x += vb.x; a.y += vb.y; a.z += vb.z; a.w += vb.w;
        *(float4*)&Qs[row][dc] = a;
        *(float4*)&Rs[row][dc] =
            *(const float4*)(p + (size_t)(j0 + row)*DMODEL + h*DHEAD + dc);
    }
    __syncthreads();

    float acc[4][4];
    #pragma unroll
    for (int nt = 0; nt < 4; nt++)
        #pragma unroll
        for (int r = 0; r < 4; r++) acc[nt][r] = 0.f;

    #pragma unroll
    for (int ks = 0; ks < 8; ks++) {
        uint32_t ah[4], al_[4];
        tf32_split(Qs[wm*16+gid  ][ks*8+tg  ], ah[0], al_[0]);
        tf32_split(Qs[wm*16+gid+8][ks*8+tg  ], ah[1], al_[1]);
        tf32_split(Qs[wm*16+gid  ][ks*8+tg+4], ah[2], al_[2]);
        tf32_split(Qs[wm*16+gid+8][ks*8+tg+4], ah[3], al_[3]);
        #pragma unroll
        for (int nt = 0; nt < 4; nt++) {
            uint32_t bh_[2], bl_[2];
            tf32_split(Rs[wn*32+nt*8+gid][ks*8+tg  ], bh_[0], bl_[0]);
            tf32_split(Rs[wn*32+nt*8+gid][ks*8+tg+4], bh_[1], bl_[1]);
            MMA_TF32(acc[nt], ah, bh_);
            MMA_TF32(acc[nt], ah, bl_);
            MMA_TF32(acc[nt], al_, bh_);
        }
    }

    int row = i0 + wm*16 + gid;
    #pragma unroll
    for (int nt = 0; nt < 4; nt++) {
        int col = j0 + wn*32 + nt*8 + 2*tg;
        *(float2*)(pos + ((size_t)bh*SEQ + row  )*SEQ + col) =
            make_float2(acc[nt][0], acc[nt][1]);
        *(float2*)(pos + ((size_t)bh*SEQ + row+8)*SEQ + col) =
            make_float2(acc[nt][2], acc[nt][3]);
    }
}

// ---------------- fused flash attention, 3xTF32 MMA --------------------------
// shifted_pos(i,j): j<=i -> pos[i, S-1-i+j]; j==i+1 -> 0; j>=i+2 -> pos[i+1, j-i-2]
__device__ __forceinline__ float posv(const float* rp, int gi, int gj) {
    if (gj <= gi)      return rp[SEQ - 1 - gi + gj];
    if (gj == gi + 1)  return 0.f;
    return rp[(size_t)SEQ + (gj - gi - 2)];   // row gi+1
}

__global__ void __launch_bounds__(256, 1) attn_tf32(
    const float* __restrict__ q, const float* __restrict__ k,
    const float* __restrict__ v, const float* __restrict__ pos,
    const float* __restrict__ ubias, float* __restrict__ head) {
    extern __shared__ float sm[];
    float* Ks = sm;                    // [64][72]
    float* Vs = sm + 64*72;            // [64][72]
    float* Ps = sm + 2*64*72;          // [128][72]
    int it = blockIdx.x, bh = blockIdx.y;
    int b = bh >> 4, h = bh & 15;
    int i0 = it * 128;
    int tid = threadIdx.x, w = tid >> 5, lane = tid & 31;
    int gid = lane >> 2, tg = lane & 3;
    const float scale = 0.125f;

    int gi0 = i0 + w*16 + gid, gi1 = gi0 + 8;
    const float* q0 = q + (size_t)(b*SEQ + gi0)*DMODEL + h*DHEAD;
    const float* q1 = q0 + (size_t)8*DMODEL;
    const float* ub = ubias + h*DHEAD;
    float qf[8][4];                    // q+u as fp32; split per ks-step
    #pragma unroll
    for (int ks = 0; ks < 8; ks++) {
        int d0 = ks*8 + tg, d1 = d0 + 4;
        qf[ks][0] = q0[d0] + ub[d0];
        qf[ks][1] = q1[d0] + ub[d0];
        qf[ks][2] = q0[d1] + ub[d1];
        qf[ks][3] = q1[d1] + ub[d1];
    }

    float o[8][4];
    #pragma unroll
    for (int dt = 0; dt < 8; dt++)
        #pragma unroll
        for (int r = 0; r < 4; r++) o[dt][r] = 0.f;
    float m0 = -1e30f, m1 = -1e30f, l0 = 0.f, l1 = 0.f;

    const float* rp0 = pos + ((size_t)bh*SEQ + gi0)*SEQ;
    const float* rp1 = pos + ((size_t)bh*SEQ + gi1)*SEQ;

    uint32_t sK = (uint32_t)__cvta_generic_to_shared(Ks);
    uint32_t sV = (uint32_t)__cvta_generic_to_shared(Vs);

    for (int j0 = 0; j0 < SEQ; j0 += 64) {
        #pragma unroll
        for (int t = 0; t < 4; t++) {
            int idx = tid + t*256;
            int row = idx >> 4, dc = (idx & 15) * 4;
            cp16(sK + (uint32_t)((row*72 + dc)*4),
                 k + (size_t)(b*SEQ + j0 + row)*DMODEL + h*DHEAD + dc);
        }
        CP_COMMIT();
        #pragma unroll
        for (int t = 0; t < 4; t++) {
            int idx = tid + t*256;
            int row = idx >> 4, dc = (idx & 15) * 4;
            cp16(sV + (uint32_t)((row*72 + dc)*4),
                 v + (size_t)(b*SEQ + j0 + row)*DMODEL + h*DHEAD + dc);
        }
        CP_COMMIT();
        CP_WAIT(1);
        __syncthreads();

        // ---- scores = (Q+u) K^T, 3xTF32 ----
        float sc[8][4];
        #pragma unroll
        for (int nt = 0; nt < 8; nt++)
            #pragma unroll
            for (int r = 0; r < 4; r++) sc[nt][r] = 0.f;
        #pragma unroll
        for (int ks = 0; ks < 8; ks++) {
            uint32_t ah[4], al_[4];
            #pragma unroll
            for (int r = 0; r < 4; r++) tf32_split(qf[ks][r], ah[r], al_[r]);
            #pragma unroll
            for (int nt = 0; nt < 8; nt++) {
                uint32_t bh_[2], bl_[2];
                tf32_split(Ks[(nt*8+gid)*72 + ks*8+tg  ], bh_[0], bl_[0]);
                tf32_split(Ks[(nt*8+gid)*72 + ks*8+tg+4], bh_[1], bl_[1]);
                MMA_TF32(sc[nt], ah, bh_);
                MMA_TF32(sc[nt], ah, bl_);
                MMA_TF32(sc[nt], al_, bh_);
            }
        }

        // ---- add shifted pos, scale, online softmax ----
        float tmax0 = -1e30f, tmax1 = -1e30f;
        #pragma unroll
        for (int nt = 0; nt < 8; nt++) {
            int gj = j0 + nt*8 + 2*tg;
            sc[nt][0] = (sc[nt][0] + posv(rp0, gi0, gj  )) * scale;
            sc[nt][1] = (sc[nt][1] + posv(rp0, gi0, gj+1)) * scale;
            sc[nt][2] = (sc[nt][2] + posv(rp1, gi1, gj  )) * scale;
            sc[nt][3] = (sc[nt][3] + posv(rp1, gi1, gj+1)) * scale;
            tmax0 = fmaxf(tmax0, fmaxf(sc[nt][0], sc[nt][1]));
            tmax1 = fmaxf(tmax1, fmaxf(sc[nt][2], sc[nt][3]));
        }
        tmax0 = fmaxf(tmax0, __shfl_xor_sync(0xffffffffu, tmax0, 1));
        tmax0 = fmaxf(tmax0, __shfl_xor_sync(0xffffffffu, tmax0, 2));
        tmax1 = fmaxf(tmax1, __shfl_xor_sync(0xffffffffu, tmax1, 1));
        tmax1 = fmaxf(tmax1, __shfl_xor_sync(0xffffffffu, tmax1, 2));
        float mn0 = fmaxf(m0, tmax0), mn1 = fmaxf(m1, tmax1);
        float c0 = __expf(m0 - mn0), c1 = __expf(m1 - mn1);
        float rs0 = 0.f, rs1 = 0.f;
        #pragma unroll
        for (int nt = 0; nt < 8; nt++) {
            float p00 = __expf(sc[nt][0] - mn0);
            float p01 = __expf(sc[nt][1] - mn0);
            float p10 = __expf(sc[nt][2] - mn1);
            float p11 = __expf(sc[nt][3] - mn1);
            rs0 += p00 + p01; rs1 += p10 + p11;
            int col = nt*8 + 2*tg;
            *(float2*)&Ps[(w*16+gid  )*72 + col] = make_float2(p00, p01);
            *(float2*)&Ps[(w*16+gid+8)*72 + col] = make_float2(p10, p11);
        }
        rs0 += __shfl_xor_sync(0xffffffffu, rs0, 1);
        rs0 += __shfl_xor_sync(0xffffffffu, rs0, 2);
        rs1 += __shfl_xor_sync(0xffffffffu, rs1, 1);
        rs1 += __shfl_xor_sync(0xffffffffu, rs1, 2);
        l0 = l0*c0 + rs0;  l1 = l1*c1 + rs1;
        m0 = mn0;          m1 = mn1;
        #pragma unroll
        for (int dt = 0; dt < 8; dt++) {
            o[dt][0] *= c0; o[dt][1] *= c0;
            o[dt][2] *= c1; o[dt][3] *= c1;
        }

        CP_WAIT(0);
        __syncthreads();

        // ---- O += P V, 3xTF32 ----
        #pragma unroll
        for (int ks = 0; ks < 8; ks++) {
            uint32_t ph[4], pl[4];
            tf32_split(Ps[(w*16+gid  )*72 + ks*8+tg  ], ph[0], pl[0]);
            tf32_split(Ps[(w*16+gid+8)*72 + ks*8+tg  ], ph[1], pl[1]);
            tf32_split(Ps[(w*16+gid  )*72 + ks*8+tg+4], ph[2], pl[2]);
            tf32_split(Ps[(w*16+gid+8)*72 + ks*8+tg+4], ph[3], pl[3]);
            #pragma unroll
            for (int dt = 0; dt < 8; dt++) {
                uint32_t vh[2], vl[2];
                tf32_split(Vs[(ks*8+tg  )*72 + dt*8+gid], vh[0], vl[0]);
                tf32_split(Vs[(ks*8+tg+4)*72 + dt*8+gid], vh[1], vl[1]);
                MMA_TF32(o[dt], ph, vh);
                MMA_TF32(o[dt], ph, vl);
                MMA_TF32(o[dt], pl, vh);
            }
        }
        __syncthreads();
    }

    float inv0 = 1.f / l0, inv1 = 1.f / l1;
    float* h0 = head + (size_t)(b*SEQ + gi0)*DMODEL + h*DHEAD;
    float* h1 = head + (size_t)(b*SEQ + gi1)*DMODEL + h*DHEAD;
    #pragma unroll
    for (int dt = 0; dt < 8; dt++) {
        int col = dt*8 + 2*tg;
        *(float2*)&h0[col] = make_float2(o[dt][0]*inv0, o[dt][1]*inv0);
        *(float2*)&h1[col] = make_float2(o[dt][2]*inv1, o[dt][3]*inv1);
    }
}

// ---------------- launch -----------------------------------------------------
extern "C" void kernel_launch(void* const* d_in, const int* in_sizes, int n_in,
                              void* d_out, int out_size) {
    const float* x    = (const float*)d_in[0];
    const float* ln_g = (const float*)d_in[1];
    const float* ln_b = (const float*)d_in[2];
    const float* Wq   = (const float*)d_in[3];
    const float* bq   = (const float*)d_in[4];
    const float* Wk   = (const float*)d_in[5];
    const float* bk   = (const float*)d_in[6];
    const float* Wv   = (const float*)d_in[7];
    const float* bv   = (const float*)d_in[8];
    const float* Wp   = (const float*)d_in[9];
    const float* Wo   = (const float*)d_in[10];
    const float* bo   = (const float*)d_in[11];
    const float* u_b  = (const float*)d_in[12];
    const float* v_b  = (const float*)d_in[13];
    float* out = (float*)d_out;

    float *pe, *xn, *qb, *kb, *vbuf, *pb, *hb, *posb;
    cudaGetSymbolAddress((void**)&pe,   g_pe);
    cudaGetSymbolAddress((void**)&xn,   g_xn);
    cudaGetSymbolAddress((void**)&qb,   g_q);
    cudaGetSymbolAddress((void**)&kb,   g_k);
    cudaGetSymbolAddress((void**)&vbuf, g_v);
    cudaGetSymbolAddress((void**)&pb,   g_p);
    cudaGetSymbolAddress((void**)&hb,   g_head);
    cudaGetSymbolAddress((void**)&posb, g_pos);

    cudaFuncSetAttribute(attn_tf32, cudaFuncAttributeMaxDynamicSharedMemorySize,
                         (2*64*72 + 128*72) * (int)sizeof(float));

    pe_kernel<<<(SEQ*(DMODEL/2) + 255)/256, 256>>>(pe);
    ln_kernel<<<NTOK, 256>>>(x, ln_g, ln_b, xn);
    dim3 gproj(DMODEL/128, NTOK/128);
    sgemm_tf32<<<gproj, 256>>>(xn, Wq, bq, qb,   NTOK, DMODEL, DMODEL);
    sgemm_tf32<<<gproj, 256>>>(xn, Wk, bk, kb,   NTOK, DMODEL, DMODEL);
    sgemm_tf32<<<gproj, 256>>>(xn, Wv, bv, vbuf, NTOK, DMODEL, DMODEL);
    dim3 gp(DMODEL/128, SEQ/128);
    sgemm_tf32<<<gp, 256>>>(pe, Wp, nullptr, pb, SEQ, DMODEL, DMODEL);
    dim3 gpos(SEQ/64, SEQ/64, BATCH*NHEAD);
    posgemm_tf32<<<gpos, 256>>>(qb, pb, v_b, posb);
    dim3 gattn(SEQ/128, BATCH*NHEAD);
    attn_tf32<<<gattn, 256, (2*64*72 + 128*72)*sizeof(float)>>>(
        qb, kb, vbuf, posb, u_b, hb);
    sgemm_tf32<<<gproj, 256>>>(hb, Wo, bo, out, NTOK, DMODEL, DMODEL);
}